// round 16
// baseline (speedup 1.0000x reference)
#include <cuda_runtime.h>
#include <cuda_bf16.h>
#include <cuda_fp16.h>
#include <cstdint>
#include <cstddef>

#define E 384
#define S 4096
#define BATCH 4
#define NROWS (BATCH * S)      // 16384
#define HID 1536
#define NH 6
#define HD 64

typedef __nv_bfloat16 bf16;

// ---------------- scratch (device globals — no runtime allocation) ----------
__device__ float  g_mod[6 * BATCH * E];
__device__ bf16   g_ymod[(size_t)NROWS * E];
__device__ bf16   g_zmod[(size_t)NROWS * E];
__device__ __half g_q[(size_t)NROWS * E];
__device__ __half g_k[(size_t)NROWS * E];
__device__ __half g_v[(size_t)NROWS * E];
__device__ bf16   g_att[(size_t)NROWS * E];
__device__ bf16   g_h[(size_t)NROWS * HID];
__device__ float  g_y[(size_t)NROWS * E];
__device__ bf16 g_wq[E * E];
__device__ bf16 g_wk[E * E];
__device__ bf16 g_wv[E * E];
__device__ bf16 g_wo[E * E];
__device__ bf16 g_ff1[E * HID];
__device__ bf16 g_ff2[HID * E];

// ---------------- small helpers --------------------------------------------
__device__ __forceinline__ uint32_t sptr(const void* p) {
    return (uint32_t)__cvta_generic_to_shared(p);
}
__device__ __forceinline__ void ldsm_x4(uint32_t* r, uint32_t addr) {
    asm volatile("ldmatrix.sync.aligned.m8n8.x4.shared.b16 {%0,%1,%2,%3}, [%4];"
                 : "=r"(r[0]), "=r"(r[1]), "=r"(r[2]), "=r"(r[3]) : "r"(addr));
}
__device__ __forceinline__ void ldsm_x4_t(uint32_t* r, uint32_t addr) {
    asm volatile("ldmatrix.sync.aligned.m8n8.x4.trans.shared.b16 {%0,%1,%2,%3}, [%4];"
                 : "=r"(r[0]), "=r"(r[1]), "=r"(r[2]), "=r"(r[3]) : "r"(addr));
}
__device__ __forceinline__ void mma_bf16(float* c, const uint32_t* a,
                                         uint32_t b0, uint32_t b1) {
    asm volatile(
        "mma.sync.aligned.m16n8k16.row.col.f32.bf16.bf16.f32 "
        "{%0,%1,%2,%3}, {%4,%5,%6,%7}, {%8,%9}, {%0,%1,%2,%3};"
        : "+f"(c[0]), "+f"(c[1]), "+f"(c[2]), "+f"(c[3])
        : "r"(a[0]), "r"(a[1]), "r"(a[2]), "r"(a[3]), "r"(b0), "r"(b1));
}
__device__ __forceinline__ void mma_f16(float* c, const uint32_t* a,
                                        uint32_t b0, uint32_t b1) {
    asm volatile(
        "mma.sync.aligned.m16n8k16.row.col.f32.f16.f16.f32 "
        "{%0,%1,%2,%3}, {%4,%5,%6,%7}, {%8,%9}, {%0,%1,%2,%3};"
        : "+f"(c[0]), "+f"(c[1]), "+f"(c[2]), "+f"(c[3])
        : "r"(a[0]), "r"(a[1]), "r"(a[2]), "r"(a[3]), "r"(b0), "r"(b1));
}
__device__ __forceinline__ void mma_f16h(uint32_t* d, const uint32_t* a,
                                         uint32_t b0, uint32_t b1) {
    asm volatile(
        "mma.sync.aligned.m16n8k16.row.col.f16.f16.f16.f16 "
        "{%0,%1}, {%2,%3,%4,%5}, {%6,%7}, {%0,%1};"
        : "+r"(d[0]), "+r"(d[1])
        : "r"(a[0]), "r"(a[1]), "r"(a[2]), "r"(a[3]), "r"(b0), "r"(b1));
}
__device__ __forceinline__ uint32_t pack_bf16(float lo, float hi) {
    __nv_bfloat162 h2 = __floats2bfloat162_rn(lo, hi);
    return *reinterpret_cast<uint32_t*>(&h2);
}
__device__ __forceinline__ uint32_t ex2h2(uint32_t x) {
    uint32_t r;
    asm("ex2.approx.f16x2 %0, %1;" : "=r"(r) : "r"(x));
    return r;
}
__device__ __forceinline__ uint32_t hadd2u(uint32_t a, uint32_t b) {
    __half2 r = __hadd2(*(__half2*)&a, *(__half2*)&b);
    return *(uint32_t*)&r;
}
__device__ __forceinline__ void cp_async16(uint32_t saddr, const void* gptr) {
    asm volatile("cp.async.cg.shared.global [%0], [%1], 16;" :: "r"(saddr), "l"(gptr));
}
__device__ __forceinline__ void cp_commit() {
    asm volatile("cp.async.commit_group;");
}
template <int N> __device__ __forceinline__ void cp_wait() {
    asm volatile("cp.async.wait_group %0;" :: "n"(N));
}

// ---------------- fused setup: weight f2b conversion + cond projections -----
struct F2B { const float* s[6]; bf16* d[6]; };
struct CondW { const float* w[6]; const float* b[6]; };

__global__ void __launch_bounds__(384)
setup_k(F2B t, const float* __restrict__ cond, CondW P, float* __restrict__ mod) {
    int bid = blockIdx.x;
    if (bid < 1152) {
        int seg, base;
        if (bid < 384) { seg = bid / 96; base = bid % 96; }
        else { seg = 4 + (bid - 384) / 384; base = (bid - 384) % 384; }
        int i = base * 384 + threadIdx.x;
        float4 v = ((const float4*)t.s[seg])[i];
        uint32_t pk[2] = {pack_bf16(v.x, v.y), pack_bf16(v.z, v.w)};
        ((uint2*)t.d[seg])[i] = *(uint2*)pk;
    } else {
        int proj = (bid - 1152) >> 2;
        int bb   = (bid - 1152) & 3;
        __shared__ float cs[E];
        int tt = threadIdx.x;
        cs[tt] = cond[bb * E + tt];
        __syncthreads();
        const float* W = P.w[proj];
        float acc = P.b[proj][tt];
#pragma unroll 4
        for (int kk = 0; kk < E; ++kk) acc = fmaf(cs[kk], W[kk * E + tt], acc);
        mod[(proj * BATCH + bb) * E + tt] = acc;
    }
}

// ---------------- LayerNorm + AdaLN modulate (bf16 out) ---------------------
__global__ void __launch_bounds__(128)
ln_mod_k(const float* __restrict__ in,
         const float* __restrict__ lnw, const float* __restrict__ lnb,
         const float* __restrict__ gamma, const float* __restrict__ beta,
         bf16* __restrict__ out) {
    int row = blockIdx.x, t = threadIdx.x;
    int bb = row >> 12;
    const float* xr = in + (size_t)row * E;
    float v0 = xr[t], v1 = xr[t + 128], v2 = xr[t + 256];
    float s  = v0 + v1 + v2;
    float sq = v0 * v0 + v1 * v1 + v2 * v2;
#pragma unroll
    for (int off = 16; off; off >>= 1) {
        s  += __shfl_xor_sync(0xffffffffu, s,  off);
        sq += __shfl_xor_sync(0xffffffffu, sq, off);
    }
    __shared__ float rs[4], rq[4];
    int w = t >> 5;
    if ((t & 31) == 0) { rs[w] = s; rq[w] = sq; }
    __syncthreads();
    s  = rs[0] + rs[1] + rs[2] + rs[3];
    sq = rq[0] + rq[1] + rq[2] + rq[3];
    float mean = s * (1.0f / E);
    float var  = sq * (1.0f / E) - mean * mean;
    float rstd = rsqrtf(var + 1e-5f);
    bf16* orow = out + (size_t)row * E;
    const float* g  = gamma + bb * E;
    const float* be = beta  + bb * E;
    float vv[3] = {v0, v1, v2};
#pragma unroll
    for (int i = 0; i < 3; ++i) {
        int e = t + i * 128;
        float val = (vv[i] - mean) * rstd * lnw[e] + lnb[e];
        orow[e] = __float2bfloat16(fmaf(val, g[e], val + be[e]));
    }
}

// ---------------- bf16 tensor-core GEMM: 4 warps, 64x64 warp tiles ----------
// Block 128x128, 64-deep K stages, 3-stage cp.async ring. Per k16 slice each
// warp issues 32 mma from 8 ldsm (4.0 mma/ldsm) — attention-style density.
#define ASTR 40
#define BSTR 136
#define A_HALF (128 * ASTR)
#define B_HALF (32 * BSTR)
#define STG_ELEMS (2 * A_HALF + 2 * B_HALF)
#define GEMM_SMEM (3 * STG_ELEMS * 2)

template <int EPI>
__global__ void __launch_bounds__(128, 2)
gemm_bf16_k(const bf16* __restrict__ A, const bf16* __restrict__ W,
            const float* __restrict__ bias, const float* __restrict__ alpha,
            const float* __restrict__ res, void* __restrict__ Cv,
            int M, int N, int K, float scale,
            const bf16* W2, const bf16* W3, void* C2, void* C3) {
    extern __shared__ char dynsmem[];
    bf16* Sm = (bf16*)dynsmem;

    int zsel = 0;
    if (EPI == 0) {
        zsel = blockIdx.z;
        if (zsel == 1) { W = W2; Cv = C2; }
        else if (zsel == 2) { W = W3; Cv = C3; }
    }

    const int tid = threadIdx.x;
    const int lane = tid & 31, wid = tid >> 5;     // 4 warps
    const int bm = blockIdx.y * 128;
    const int bn = blockIdx.x * 128;
    const int warp_m = wid >> 1, warp_n = wid & 1; // 2x2 warp grid

    // cp.async mappings (128 threads)
    const int a_row = tid >> 2, a_col = (tid & 3) * 8;   // 32 rows x 32 cols
    const int b_row = tid >> 4, b_col = (tid & 15) * 8;  // 8 rows x 128 cols
    const bf16* Abase = A + (size_t)(bm + a_row) * K + a_col;
    const bf16* Wbase = W + (size_t)b_row * N + bn + b_col;

    const int nk = K / 64;
    auto load_stage = [&](int st, int kb) {
        bf16* Ast = Sm + st * STG_ELEMS;
        bf16* Bst = Ast + 2 * A_HALF;
#pragma unroll
        for (int h = 0; h < 2; ++h) {
            const bf16* Ab = Abase + kb * 64 + h * 32;
            bf16* Ah = Ast + h * A_HALF;
#pragma unroll
            for (int p = 0; p < 4; ++p)
                cp_async16(sptr(&Ah[(a_row + p * 32) * ASTR + a_col]),
                           Ab + (size_t)(p * 32) * K);
            const bf16* Bb = Wbase + (size_t)(kb * 64 + h * 32) * N;
            bf16* Bh = Bst + h * B_HALF;
#pragma unroll
            for (int p = 0; p < 4; ++p)
                cp_async16(sptr(&Bh[(b_row + p * 8) * BSTR + b_col]),
                           Bb + (size_t)(p * 8) * N);
        }
        cp_commit();
    };

    load_stage(0, 0);
    if (nk > 1) load_stage(1, 1);

    float acc[4][8][4] = {};
    const int lrow = lane & 15, lcol = (lane >> 4) * 8;
    const int tb_row = (lane & 7) + ((lane & 8) ? 8 : 0);
    const int tb_col = (lane & 16) ? 8 : 0;

    int st = 0;
    for (int kb = 0; kb < nk; ++kb) {
        if (kb + 1 < nk) cp_wait<1>(); else cp_wait<0>();
        __syncthreads();
        if (kb + 2 < nk) {
            int nst = st + 2; if (nst >= 3) nst -= 3;
            load_stage(nst, kb + 2);
        }
        const bf16* Ast = Sm + st * STG_ELEMS;
        const bf16* Bst = Ast + 2 * A_HALF;
#pragma unroll
        for (int h = 0; h < 2; ++h) {
            const bf16* Ah = Ast + h * A_HALF;
            const bf16* Bh = Bst + h * B_HALF;
#pragma unroll
            for (int ks = 0; ks < 2; ++ks) {
                uint32_t af[4][4];
#pragma unroll
                for (int mi = 0; mi < 4; ++mi)
                    ldsm_x4(af[mi], sptr(&Ah[(warp_m * 64 + mi * 16 + lrow) * ASTR + ks * 16 + lcol]));
                uint32_t bf_[4][4];
#pragma unroll
                for (int ni2 = 0; ni2 < 4; ++ni2)
                    ldsm_x4_t(bf_[ni2], sptr(&Bh[(ks * 16 + tb_row) * BSTR + warp_n * 64 + ni2 * 16 + tb_col]));
#pragma unroll
                for (int mi = 0; mi < 4; ++mi) {
#pragma unroll
                    for (int ni2 = 0; ni2 < 4; ++ni2) {
                        mma_bf16(acc[mi][ni2 * 2],     af[mi], bf_[ni2][0], bf_[ni2][1]);
                        mma_bf16(acc[mi][ni2 * 2 + 1], af[mi], bf_[ni2][2], bf_[ni2][3]);
                    }
                }
            }
        }
        if (++st == 3) st = 0;
    }

    const float sc = (EPI == 0 && zsel == 0) ? scale : 1.0f;
#pragma unroll
    for (int mi = 0; mi < 4; ++mi) {
#pragma unroll
        for (int rr = 0; rr < 2; ++rr) {
            int row = bm + warp_m * 64 + mi * 16 + (lane >> 2) + rr * 8;
            int bIdx = row >> 12;
            size_t rowoff = (size_t)row * N;
#pragma unroll
            for (int ni = 0; ni < 8; ++ni) {
                int col = bn + warp_n * 64 + ni * 8 + (lane & 3) * 2;
                float c0 = acc[mi][ni][rr * 2], c1 = acc[mi][ni][rr * 2 + 1];
                if (EPI == 0) {
                    __half2 hv = __floats2half2_rn(c0 * sc, c1 * sc);
                    *(uint32_t*)((__half*)Cv + rowoff + col) = *(uint32_t*)&hv;
                } else if (EPI == 2) {
                    float t0 = fmaxf(c0 + bias[col], 0.0f);
                    float t1 = fmaxf(c1 + bias[col + 1], 0.0f);
                    *(uint32_t*)((bf16*)Cv + rowoff + col) = pack_bf16(t0, t1);
                } else if (EPI == 1) {
                    float2 r = *(const float2*)(res + rowoff + col);
                    float a0f = alpha[bIdx * E + col], a1f = alpha[bIdx * E + col + 1];
                    *(float2*)((float*)Cv + rowoff + col) =
                        make_float2(r.x + c0 * a0f, r.y + c1 * a1f);
                } else {
                    float2 r = *(const float2*)(res + rowoff + col);
                    float a0f = alpha[bIdx * E + col], a1f = alpha[bIdx * E + col + 1];
                    *(float2*)((float*)Cv + rowoff + col) =
                        make_float2(r.x + (c0 + bias[col]) * a0f,
                                    r.y + (c1 + bias[col + 1]) * a1f);
                }
            }
        }
    }
}

// ---------------- flash attention: 128-key tiles, 2-stage ring --------------
// (unchanged from R15 winner)
#define KSTRIDE 72
#define KV_ROWS 128
#define K_STG (KV_ROWS * KSTRIDE)
#define ATT_STG (2 * K_STG)
#define ATT_SMEM (2 * ATT_STG * 2)

__global__ void __launch_bounds__(128, 2)
attn_mma_k(const __half* __restrict__ q, const __half* __restrict__ k,
           const __half* __restrict__ v, bf16* __restrict__ out) {
    extern __shared__ char dynsmem[];
    __half* Sm = (__half*)dynsmem;

    const int tid = threadIdx.x;
    const int lane = tid & 31, w = tid >> 5;
    const int bh = blockIdx.y;
    const int b = bh / NH, h = bh % NH;
    const int q0 = blockIdx.x * 128;

    const int kv_row = tid >> 3;
    const int kv_col = (tid & 7) * 8;

#pragma unroll
    for (int p = 0; p < 8; ++p) {
        int row = kv_row + p * 16;
        *(uint4*)&Sm[row * KSTRIDE + kv_col] =
            *(const uint4*)(q + ((size_t)(b * S + q0 + row)) * E + h * HD + kv_col);
    }
    __syncthreads();

    uint32_t a_q[2][4][4];
    {
        int lrow = lane & 15, lcol = (lane >> 4) * 8;
#pragma unroll
        for (int rb = 0; rb < 2; ++rb)
#pragma unroll
            for (int kc = 0; kc < 4; ++kc)
                ldsm_x4(a_q[rb][kc],
                        sptr(&Sm[(w * 32 + rb * 16 + lrow) * KSTRIDE + kc * 16 + lcol]));
    }
    __syncthreads();

    const __half* kbase = k + ((size_t)(b * S) + kv_row) * E + h * HD + kv_col;
    const __half* vbase = v + ((size_t)(b * S) + kv_row) * E + h * HD + kv_col;
    auto load_kv = [&](int st, int kt) {
        __half* Kst = Sm + st * ATT_STG;
        __half* Vst = Kst + K_STG;
        const __half* kp = kbase + (size_t)(kt * KV_ROWS) * E;
        const __half* vp = vbase + (size_t)(kt * KV_ROWS) * E;
#pragma unroll
        for (int p = 0; p < 8; ++p) {
            cp_async16(sptr(&Kst[(kv_row + p * 16) * KSTRIDE + kv_col]),
                       kp + (size_t)(p * 16) * E);
            cp_async16(sptr(&Vst[(kv_row + p * 16) * KSTRIDE + kv_col]),
                       vp + (size_t)(p * 16) * E);
        }
        cp_commit();
    };

    load_kv(0, 0);
    load_kv(1, 1);

    const int kb_row = (lane & 7) + ((lane & 16) ? 8 : 0);
    const int kb_col = (lane & 8) ? 8 : 0;
    const int vb_row = (lane & 7) + ((lane & 8) ? 8 : 0);
    const int vb_col = (lane & 16) ? 8 : 0;

    float l[2][2] = {};
    float o[2][8][4] = {};
    const int nt = S / KV_ROWS;

#pragma unroll 1
    for (int kt = 0; kt < nt; ++kt) {
        cp_wait<1>();
        __syncthreads();
        const int st = kt & 1;
        const __half* Kst = Sm + st * ATT_STG;
        const __half* Vst = Kst + K_STG;

        uint32_t s0[2][16], s1[2][16];
#pragma unroll
        for (int rb = 0; rb < 2; ++rb)
#pragma unroll
            for (int i = 0; i < 16; ++i) { s0[rb][i] = 0u; s1[rb][i] = 0u; }
#pragma unroll
        for (int kc = 0; kc < 4; ++kc) {
#pragma unroll
            for (int nb2 = 0; nb2 < 4; ++nb2) {
                uint32_t bb[4];
                ldsm_x4(bb, sptr(&Kst[(nb2 * 16 + kb_row) * KSTRIDE + kc * 16 + kb_col]));
                mma_f16h(&s0[0][nb2 * 4],     a_q[0][kc], bb[0], bb[1]);
                mma_f16h(&s0[0][nb2 * 4 + 2], a_q[0][kc], bb[2], bb[3]);
                mma_f16h(&s0[1][nb2 * 4],     a_q[1][kc], bb[0], bb[1]);
                mma_f16h(&s0[1][nb2 * 4 + 2], a_q[1][kc], bb[2], bb[3]);
            }
        }
#pragma unroll
        for (int kc = 0; kc < 4; ++kc) {
#pragma unroll
            for (int nb2 = 0; nb2 < 4; ++nb2) {
                uint32_t bb[4];
                ldsm_x4(bb, sptr(&Kst[((64 + nb2 * 16) + kb_row) * KSTRIDE + kc * 16 + kb_col]));
                mma_f16h(&s1[0][nb2 * 4],     a_q[0][kc], bb[0], bb[1]);
                mma_f16h(&s1[0][nb2 * 4 + 2], a_q[0][kc], bb[2], bb[3]);
                mma_f16h(&s1[1][nb2 * 4],     a_q[1][kc], bb[0], bb[1]);
                mma_f16h(&s1[1][nb2 * 4 + 2], a_q[1][kc], bb[2], bb[3]);
            }
        }

#pragma unroll
        for (int rb = 0; rb < 2; ++rb)
#pragma unroll
            for (int i = 0; i < 16; ++i) s0[rb][i] = ex2h2(s0[rb][i]);

#pragma unroll
        for (int kc = 0; kc < 4; ++kc) {
#pragma unroll
            for (int nb2 = 0; nb2 < 4; ++nb2) {
                uint32_t bb[4];
                ldsm_x4_t(bb, sptr(&Vst[(kc * 16 + vb_row) * KSTRIDE + nb2 * 16 + vb_col]));
                mma_f16(o[0][nb2 * 2],     &s0[0][kc * 4], bb[0], bb[1]);
                mma_f16(o[0][nb2 * 2 + 1], &s0[0][kc * 4], bb[2], bb[3]);
                mma_f16(o[1][nb2 * 2],     &s0[1][kc * 4], bb[0], bb[1]);
                mma_f16(o[1][nb2 * 2 + 1], &s0[1][kc * 4], bb[2], bb[3]);
            }
        }

#pragma unroll
        for (int rb = 0; rb < 2; ++rb)
#pragma unroll
            for (int i = 0; i < 16; ++i) s1[rb][i] = ex2h2(s1[rb][i]);

#pragma unroll
        for (int kc = 0; kc < 4; ++kc) {
#pragma unroll
            for (int nb2 = 0; nb2 < 4; ++nb2) {
                uint32_t bb[4];
                ldsm_x4_t(bb, sptr(&Vst[((64 + kc * 16) + vb_row) * KSTRIDE + nb2 * 16 + vb_col]));
                mma_f16(o[0][nb2 * 2],     &s1[0][kc * 4], bb[0], bb[1]);
                mma_f16(o[0][nb2 * 2 + 1], &s1[0][kc * 4], bb[2], bb[3]);
                mma_f16(o[1][nb2 * 2],     &s1[1][kc * 4], bb[0], bb[1]);
                mma_f16(o[1][nb2 * 2 + 1], &s1[1][kc * 4], bb[2], bb[3]);
            }
        }

        if (kt + 2 < nt) load_kv(st, kt + 2);
        else cp_commit();

#pragma unroll
        for (int rb = 0; rb < 2; ++rb) {
            uint32_t hA = hadd2u(
                hadd2u(hadd2u(hadd2u(s0[rb][0], s0[rb][2]), hadd2u(s0[rb][4], s0[rb][6])),
                       hadd2u(hadd2u(s0[rb][8], s0[rb][10]), hadd2u(s0[rb][12], s0[rb][14]))),
                hadd2u(hadd2u(hadd2u(s1[rb][0], s1[rb][2]), hadd2u(s1[rb][4], s1[rb][6])),
                       hadd2u(hadd2u(s1[rb][8], s1[rb][10]), hadd2u(s1[rb][12], s1[rb][14]))));
            uint32_t hB = hadd2u(
                hadd2u(hadd2u(hadd2u(s0[rb][1], s0[rb][3]), hadd2u(s0[rb][5], s0[rb][7])),
                       hadd2u(hadd2u(s0[rb][9], s0[rb][11]), hadd2u(s0[rb][13], s0[rb][15]))),
                hadd2u(hadd2u(hadd2u(s1[rb][1], s1[rb][3]), hadd2u(s1[rb][5], s1[rb][7])),
                       hadd2u(hadd2u(s1[rb][9], s1[rb][11]), hadd2u(s1[rb][13], s1[rb][15]))));
            __half2 hA2 = *(__half2*)&hA, hB2 = *(__half2*)&hB;
            l[rb][0] += __low2float(hA2) + __high2float(hA2);
            l[rb][1] += __low2float(hB2) + __high2float(hB2);
        }
    }

#pragma unroll
    for (int rb = 0; rb < 2; ++rb) {
#pragma unroll
        for (int rr = 0; rr < 2; ++rr) {
            l[rb][rr] += __shfl_xor_sync(0xffffffffu, l[rb][rr], 1);
            l[rb][rr] += __shfl_xor_sync(0xffffffffu, l[rb][rr], 2);
        }
    }

#pragma unroll
    for (int rb = 0; rb < 2; ++rb) {
        float i0 = 1.0f / l[rb][0], i1 = 1.0f / l[rb][1];
        int row0 = q0 + w * 32 + rb * 16 + (lane >> 2);
        int colb = h * HD + (lane & 3) * 2;
        bf16* out0 = out + ((size_t)(b * S + row0)) * E + colb;
        bf16* out1 = out0 + 8 * (size_t)E;
#pragma unroll
        for (int j = 0; j < 8; ++j) {
            *(uint32_t*)(out0 + j * 8) = pack_bf16(o[rb][j][0] * i0, o[rb][j][1] * i0);
            *(uint32_t*)(out1 + j * 8) = pack_bf16(o[rb][j][2] * i1, o[rb][j][3] * i1);
        }
    }
}

// ---------------- launcher ---------------------------------------------------
extern "C" void kernel_launch(void* const* d_in, const int* in_sizes, int n_in,
                              void* d_out, int out_size) {
    const float* x    = (const float*)d_in[0];
    const float* cond = (const float*)d_in[1];
    const float* ln1w = (const float*)d_in[14];
    const float* ln1b = (const float*)d_in[15];
    const float* ln2w = (const float*)d_in[16];
    const float* ln2b = (const float*)d_in[17];
    const float* ff1b = (const float*)d_in[23];
    const float* ff2b = (const float*)d_in[25];

    float *mod, *y;
    bf16 *ymod, *zmod, *att, *hb;
    __half *qb, *kb, *vb;
    bf16 *wqb, *wkb, *wvb, *wob, *ff1w_, *ff2w_;
    cudaGetSymbolAddress((void**)&mod,   g_mod);
    cudaGetSymbolAddress((void**)&ymod,  g_ymod);
    cudaGetSymbolAddress((void**)&zmod,  g_zmod);
    cudaGetSymbolAddress((void**)&qb,    g_q);
    cudaGetSymbolAddress((void**)&kb,    g_k);
    cudaGetSymbolAddress((void**)&vb,    g_v);
    cudaGetSymbolAddress((void**)&att,   g_att);
    cudaGetSymbolAddress((void**)&hb,    g_h);
    cudaGetSymbolAddress((void**)&y,     g_y);
    cudaGetSymbolAddress((void**)&wqb,   g_wq);
    cudaGetSymbolAddress((void**)&wkb,   g_wk);
    cudaGetSymbolAddress((void**)&wvb,   g_wv);
    cudaGetSymbolAddress((void**)&wob,   g_wo);
    cudaGetSymbolAddress((void**)&ff1w_, g_ff1);
    cudaGetSymbolAddress((void**)&ff2w_, g_ff2);

    cudaFuncSetAttribute(gemm_bf16_k<0>, cudaFuncAttributeMaxDynamicSharedMemorySize, GEMM_SMEM);
    cudaFuncSetAttribute(gemm_bf16_k<1>, cudaFuncAttributeMaxDynamicSharedMemorySize, GEMM_SMEM);
    cudaFuncSetAttribute(gemm_bf16_k<2>, cudaFuncAttributeMaxDynamicSharedMemorySize, GEMM_SMEM);
    cudaFuncSetAttribute(gemm_bf16_k<3>, cudaFuncAttributeMaxDynamicSharedMemorySize, GEMM_SMEM);
    cudaFuncSetAttribute(attn_mma_k,     cudaFuncAttributeMaxDynamicSharedMemorySize, ATT_SMEM);

    CondW P;
    P.w[0] = (const float*)d_in[2];  P.b[0] = (const float*)d_in[3];
    P.w[1] = (const float*)d_in[4];  P.b[1] = (const float*)d_in[5];
    P.w[2] = (const float*)d_in[6];  P.b[2] = (const float*)d_in[7];
    P.w[3] = (const float*)d_in[8];  P.b[3] = (const float*)d_in[9];
    P.w[4] = (const float*)d_in[10]; P.b[4] = (const float*)d_in[11];
    P.w[5] = (const float*)d_in[12]; P.b[5] = (const float*)d_in[13];

    const float* gamma1 = mod + 0 * BATCH * E;
    const float* beta1  = mod + 1 * BATCH * E;
    const float* alpha1 = mod + 2 * BATCH * E;
    const float* gamma2 = mod + 3 * BATCH * E;
    const float* beta2  = mod + 4 * BATCH * E;
    const float* alpha2 = mod + 5 * BATCH * E;

    F2B T;
    T.s[0] = (const float*)d_in[18]; T.d[0] = wqb;
    T.s[1] = (const float*)d_in[19]; T.d[1] = wkb;
    T.s[2] = (const float*)d_in[20]; T.d[2] = wvb;
    T.s[3] = (const float*)d_in[21]; T.d[3] = wob;
    T.s[4] = (const float*)d_in[22]; T.d[4] = ff1w_;
    T.s[5] = (const float*)d_in[24]; T.d[5] = ff2w_;

    setup_k<<<1176, 384>>>(T, cond, P, mod);

    ln_mod_k<<<NROWS, 128>>>(x, ln1w, ln1b, gamma1, beta1, ymod);

    dim3 gQKV(E / 128, NROWS / 128, 3);
    gemm_bf16_k<0><<<gQKV, 128, GEMM_SMEM>>>(ymod, wqb, nullptr, nullptr, nullptr, qb,
                                             NROWS, E, E, 0.18033688f, wkb, wvb, kb, vb);

    attn_mma_k<<<dim3(S / 128, BATCH * NH), 128, ATT_SMEM>>>(qb, kb, vb, att);

    dim3 gE(E / 128, NROWS / 128);
    gemm_bf16_k<1><<<gE, 128, GEMM_SMEM>>>(att, wob, nullptr, alpha1, x, y,
                                           NROWS, E, E, 1.0f, nullptr, nullptr, nullptr, nullptr);

    ln_mod_k<<<NROWS, 128>>>(y, ln2w, ln2b, gamma2, beta2, zmod);

    dim3 gH(HID / 128, NROWS / 128);
    gemm_bf16_k<2><<<gH, 128, GEMM_SMEM>>>(zmod, ff1w_, ff1b, nullptr, nullptr, hb,
                                           NROWS, HID, E, 1.0f, nullptr, nullptr, nullptr, nullptr);
    gemm_bf16_k<3><<<gE, 128, GEMM_SMEM>>>(hb, ff2w_, ff2b, alpha2, y, d_out,
                                           NROWS, E, HID, 1.0f, nullptr, nullptr, nullptr, nullptr);
}